// round 1
// baseline (speedup 1.0000x reference)
#include <cuda_runtime.h>

#define BB 2
#define CC 256
#define HH 128
#define WW 128
#define H2 256
#define W2 256

// scratch (no allocations allowed)
__device__ float g_mean[BB * HH * WW];
__device__ float g_kern[BB * 9 * H2 * W2];

// ---------------------------------------------------------------------------
// Kernel A: channel mean  mean[b,h,w] = (1/256) * sum_c x[b,c,h,w]
// ---------------------------------------------------------------------------
__global__ void mean_kernel(const float* __restrict__ x) {
    int h = blockIdx.x;
    int b = blockIdx.y;
    int w = threadIdx.x;
    const float* p = x + (((size_t)b * CC) * HH + h) * WW + w;
    float s0 = 0.f, s1 = 0.f, s2 = 0.f, s3 = 0.f;
    const size_t stride = (size_t)HH * WW;
#pragma unroll 4
    for (int c = 0; c < CC; c += 4) {
        s0 += p[(size_t)(c + 0) * stride];
        s1 += p[(size_t)(c + 1) * stride];
        s2 += p[(size_t)(c + 2) * stride];
        s3 += p[(size_t)(c + 3) * stride];
    }
    g_mean[(b * HH + h) * WW + w] = (s0 + s1 + s2 + s3) * (1.0f / CC);
}

// ---------------------------------------------------------------------------
// Kernel B: fused offset-conv + tanh + center + inverse-distance kernels +
//           grad gating + softmax  ->  g_kern[b,k,y,x]
// ---------------------------------------------------------------------------
__global__ void kern_kernel(const float* __restrict__ Woff,
                            const float* __restrict__ boff) {
    __shared__ float sW[50];
    __shared__ float sb[2];
    int t = threadIdx.x;
    if (t < 50) sW[t] = Woff[t];
    if (t < 2) sb[t] = boff[t];
    __syncthreads();

    int idx = blockIdx.x * blockDim.x + t;     // [0, B*H2*W2)
    int xq = idx & (W2 - 1);
    int y  = (idx >> 8) & (H2 - 1);
    int b  = idx >> 16;

    const float* m = g_mean + b * HH * WW;

    // 5x5 conv on nearest-up2(mean), zero padded by 2 (both offset channels)
    float a0 = 0.f, a1 = 0.f;
#pragma unroll
    for (int u = 0; u < 5; ++u) {
        int Y = y - 2 + u;
        if (Y < 0 || Y >= H2) continue;
        int hh = Y >> 1;
#pragma unroll
        for (int v = 0; v < 5; ++v) {
            int X = xq - 2 + v;
            if (X < 0 || X >= W2) continue;
            float mv = m[hh * WW + (X >> 1)];
            a0 = fmaf(mv, sW[u * 5 + v], a0);
            a1 = fmaf(mv, sW[25 + u * 5 + v], a1);
        }
    }
    float s0 = ((xq & 1) ? 0.25f : -0.25f) + 0.25f * tanhf(a0 + sb[0]);
    float s1 = ((y  & 1) ? 0.25f : -0.25f) + 0.25f * tanhf(a1 + sb[1]);

    int hh = y >> 1, ww = xq >> 1;
    float mc = m[hh * WW + ww];

    float logit[9];
    float mx = -1e30f;
#pragma unroll
    for (int k = 0; k < 9; ++k) {
        int di = k / 3 - 1;          // height offset (pairs with shift ch1)
        int dj = k % 3 - 1;          // width  offset (pairs with shift ch0)
        int hn = hh + di, wn = ww + dj;
        float pm = (hn >= 0 && hn < HH && wn >= 0 && wn < WW)
                   ? m[hn * WW + wn] : 0.f;
        float d = pm - mc;
        float g = 1.f / fmaf(d, d, 1.f);
        float e0 = s0 - (float)dj;
        float e1 = s1 - (float)di;
        float d2 = fmaf(e0, e0, fmaf(e1, e1, 0.2f));
        float kv = g / d2;
        logit[k] = kv;
        mx = fmaxf(mx, kv);
    }
    float ev[9];
    float sum = 0.f;
#pragma unroll
    for (int k = 0; k < 9; ++k) { ev[k] = expf(logit[k] - mx); sum += ev[k]; }
    float inv = 1.f / sum;
#pragma unroll
    for (int k = 0; k < 9; ++k)
        g_kern[((b * 9 + k) * H2 + y) * W2 + xq] = ev[k] * inv;
}

// ---------------------------------------------------------------------------
// Kernel C: CARAFE apply.
// Block = (c-group of 64, 2-input-row stripe, batch). 256 threads.
// Thread = one input pixel (h,w) -> 2x2 output cell, 36 softmax weights in
// registers (18 float2 loads), x stripe double-buffered in smem.
// ---------------------------------------------------------------------------
__global__ void __launch_bounds__(256, 3)
carafe_kernel(const float* __restrict__ x, float* __restrict__ out) {
    __shared__ float xs[2][4][WW];        // rows h0-1 .. h0+2, double buffered

    int b  = blockIdx.z;
    int h0 = blockIdx.y * 2;
    int c0 = blockIdx.x * 64;
    int t  = threadIdx.x;
    int r  = t >> 7;                      // 0..1 local input row
    int w  = t & 127;                     // input column
    int h  = h0 + r;

    // hoist the 36 softmax weights for this 2x2 output cell into registers
    const float2* kp = (const float2*)(g_kern + (size_t)b * 9 * H2 * W2);
    float2 wk[2][9];                      // [p][k] -> (q=0, q=1)
#pragma unroll
    for (int p = 0; p < 2; ++p) {
        int y = 2 * h + p;
#pragma unroll
        for (int k = 0; k < 9; ++k)
            wk[p][k] = kp[((size_t)k * H2 + y) * (W2 / 2) + w];
    }

    const size_t plane = (size_t)HH * WW;
    const float* xb = x + (size_t)b * CC * plane;

    // prologue: load channel c0 into buffer 0
    {
        const float* xc = xb + (size_t)c0 * plane;
#pragma unroll
        for (int j = 0; j < 2; ++j) {
            int rr  = r + 2 * j;          // 0..3
            int row = h0 - 1 + rr;
            xs[0][rr][w] = (row >= 0 && row < HH) ? xc[row * WW + w] : 0.f;
        }
    }

    for (int ci = 0; ci < 64; ++ci) {
        int c   = c0 + ci;
        int buf = ci & 1;
        __syncthreads();

        if (ci + 1 < 64) {
            const float* xc = xb + (size_t)(c + 1) * plane;
#pragma unroll
            for (int j = 0; j < 2; ++j) {
                int rr  = r + 2 * j;
                int row = h0 - 1 + rr;
                xs[buf ^ 1][rr][w] = (row >= 0 && row < HH) ? xc[row * WW + w] : 0.f;
            }
        }

        // 3x3 patch around (h, w), zero padded horizontally
        float xp[9];
#pragma unroll
        for (int di = 0; di < 3; ++di) {
#pragma unroll
            for (int dj = 0; dj < 3; ++dj) {
                int ww2 = w - 1 + dj;
                xp[di * 3 + dj] = (ww2 >= 0 && ww2 < WW) ? xs[buf][r + di][ww2] : 0.f;
            }
        }

        float2 acc0 = make_float2(0.f, 0.f);
        float2 acc1 = make_float2(0.f, 0.f);
#pragma unroll
        for (int k = 0; k < 9; ++k) {
            float v = xp[k];
            acc0.x = fmaf(wk[0][k].x, v, acc0.x);
            acc0.y = fmaf(wk[0][k].y, v, acc0.y);
            acc1.x = fmaf(wk[1][k].x, v, acc1.x);
            acc1.y = fmaf(wk[1][k].y, v, acc1.y);
        }

        float2* op = (float2*)(out + (((size_t)(b * CC + c)) * H2 + 2 * h) * W2);
        op[w] = acc0;
        op[(W2 / 2) + w] = acc1;          // row 2h+1
    }
}

extern "C" void kernel_launch(void* const* d_in, const int* in_sizes, int n_in,
                              void* d_out, int out_size) {
    const float* x    = (const float*)d_in[0];
    const float* Woff = (const float*)d_in[1];
    const float* boff = (const float*)d_in[2];
    float* out = (float*)d_out;

    mean_kernel<<<dim3(HH, BB), WW>>>(x);
    kern_kernel<<<(BB * H2 * W2) / 256, 256>>>(Woff, boff);
    carafe_kernel<<<dim3(CC / 64, HH / 2, BB), 256>>>(x, out);
}

// round 2
// speedup vs baseline: 2.0746x; 2.0746x over previous
#include <cuda_runtime.h>

#define BB 2
#define CC 256
#define HH 128
#define WW 128
#define H2 256
#define W2 256
#define PLANE (HH * WW)

#define CPG 16      // channels per carafe block
#define STAGE 4     // channels per pipeline stage

// scratch (no allocations allowed)
__device__ float g_part[BB * 8 * PLANE];            // partial channel sums
__device__ float g_mean[BB * PLANE];
__device__ float g_kern[BB * 9 * H2 * W2];

// ---------------------------------------------------------------------------
// Kernel A1: partial channel sums (32 channels per block-slice, float4 pixels)
// ---------------------------------------------------------------------------
__global__ void mean1_kernel(const float* __restrict__ x) {
    int t  = threadIdx.x;
    int p4 = blockIdx.x * 256 + t;          // float4-pixel index [0, PLANE/4)
    int cg = blockIdx.y;                    // channel group [0,8)
    int b  = blockIdx.z;
    const float4* xp = (const float4*)x
                     + (size_t)(b * CC + cg * 32) * (PLANE / 4) + p4;
    float4 s = make_float4(0.f, 0.f, 0.f, 0.f);
#pragma unroll
    for (int c = 0; c < 32; ++c) {
        float4 v = xp[(size_t)c * (PLANE / 4)];
        s.x += v.x; s.y += v.y; s.z += v.z; s.w += v.w;
    }
    ((float4*)g_part)[((size_t)(b * 8 + cg)) * (PLANE / 4) + p4] = s;
}

// ---------------------------------------------------------------------------
// Kernel A2: combine partials -> mean
// ---------------------------------------------------------------------------
__global__ void mean2_kernel() {
    int idx = blockIdx.x * 256 + threadIdx.x;   // [0, BB*PLANE/4)
    int b   = idx / (PLANE / 4);
    int p4  = idx % (PLANE / 4);
    float4 s = make_float4(0.f, 0.f, 0.f, 0.f);
#pragma unroll
    for (int g = 0; g < 8; ++g) {
        float4 v = ((const float4*)g_part)[((size_t)(b * 8 + g)) * (PLANE / 4) + p4];
        s.x += v.x; s.y += v.y; s.z += v.z; s.w += v.w;
    }
    const float sc = 1.0f / CC;
    s.x *= sc; s.y *= sc; s.z *= sc; s.w *= sc;
    ((float4*)g_mean)[(size_t)b * (PLANE / 4) + p4] = s;
}

// ---------------------------------------------------------------------------
// Kernel B: fused offset-conv + tanh + center + inverse-distance kernels +
//           grad gating + softmax  ->  g_kern[b,k,y,x]   (fast-math versions)
// ---------------------------------------------------------------------------
__device__ __forceinline__ float fast_tanh(float x) {
    float e = __expf(2.0f * x);
    return __fdividef(e - 1.0f, e + 1.0f);
}

__global__ void kern_kernel(const float* __restrict__ Woff,
                            const float* __restrict__ boff) {
    __shared__ float sW[50];
    __shared__ float sb[2];
    int t = threadIdx.x;
    if (t < 50) sW[t] = Woff[t];
    if (t < 2) sb[t] = boff[t];
    __syncthreads();

    int idx = blockIdx.x * blockDim.x + t;     // [0, B*H2*W2)
    int xq = idx & (W2 - 1);
    int y  = (idx >> 8) & (H2 - 1);
    int b  = idx >> 16;

    const float* m = g_mean + b * PLANE;

    // 5x5 conv on nearest-up2(mean), zero padded by 2 (both offset channels)
    float a0 = 0.f, a1 = 0.f;
#pragma unroll
    for (int u = 0; u < 5; ++u) {
        int Y = y - 2 + u;
        if (Y < 0 || Y >= H2) continue;
        int hh = Y >> 1;
#pragma unroll
        for (int v = 0; v < 5; ++v) {
            int X = xq - 2 + v;
            if (X < 0 || X >= W2) continue;
            float mv = m[hh * WW + (X >> 1)];
            a0 = fmaf(mv, sW[u * 5 + v], a0);
            a1 = fmaf(mv, sW[25 + u * 5 + v], a1);
        }
    }
    float s0 = ((xq & 1) ? 0.25f : -0.25f) + 0.25f * fast_tanh(a0 + sb[0]);
    float s1 = ((y  & 1) ? 0.25f : -0.25f) + 0.25f * fast_tanh(a1 + sb[1]);

    int hh = y >> 1, ww = xq >> 1;
    float mc = m[hh * WW + ww];

    float logit[9];
    float mx = -1e30f;
#pragma unroll
    for (int k = 0; k < 9; ++k) {
        int di = k / 3 - 1;          // height offset (pairs with shift ch1)
        int dj = k % 3 - 1;          // width  offset (pairs with shift ch0)
        int hn = hh + di, wn = ww + dj;
        float pm = (hn >= 0 && hn < HH && wn >= 0 && wn < WW)
                   ? m[hn * WW + wn] : 0.f;
        float d = pm - mc;
        float e0 = s0 - (float)dj;
        float e1 = s1 - (float)di;
        float d2 = fmaf(e0, e0, fmaf(e1, e1, 0.2f));
        float kv = __fdividef(1.f, fmaf(d, d, 1.f) * d2);
        logit[k] = kv;
        mx = fmaxf(mx, kv);
    }
    float ev[9];
    float sum = 0.f;
#pragma unroll
    for (int k = 0; k < 9; ++k) { ev[k] = __expf(logit[k] - mx); sum += ev[k]; }
    float inv = __fdividef(1.f, sum);
#pragma unroll
    for (int k = 0; k < 9; ++k)
        g_kern[((b * 9 + k) * H2 + y) * W2 + xq] = ev[k] * inv;
}

// ---------------------------------------------------------------------------
// Kernel C: CARAFE apply.
// Block = (16-channel group, 2-input-row stripe full width, batch).
// 256 threads; thread = one input pixel (h,w) -> 2x2 output cell.
// 36 softmax weights hoisted to registers; x planes loaded 4 channels per
// double-buffered pipeline stage (float4 fills); packed f32x2 FFMA.
// ---------------------------------------------------------------------------
__global__ void __launch_bounds__(256)
carafe_kernel(const float* __restrict__ x, float* __restrict__ out) {
    __shared__ float xs[2][STAGE][4 * WW];   // 16 KB

    int b  = blockIdx.z;
    int h0 = blockIdx.y * 2;
    int c0 = blockIdx.x * CPG;
    int t  = threadIdx.x;
    int r  = t >> 7;                  // 0..1 local input row
    int w  = t & 127;                 // input column
    int h  = h0 + r;

    // hoist the 36 softmax weights for this 2x2 output cell (as packed f32x2)
    const unsigned long long* kp =
        (const unsigned long long*)(g_kern + (size_t)b * 9 * H2 * W2);
    unsigned long long wk0[9], wk1[9];
#pragma unroll
    for (int k = 0; k < 9; ++k) {
        wk0[k] = kp[((size_t)k * H2 + 2 * h)     * (W2 / 2) + w];
        wk1[k] = kp[((size_t)k * H2 + 2 * h + 1) * (W2 / 2) + w];
    }

    const float* xb = x + (size_t)b * CC * PLANE;

    // stage loader: 4 channel planes x 4 rows x 128 cols = 512 float4
    auto load_stage = [&](int s, int buf) {
        int cb = c0 + s * STAGE;
#pragma unroll
        for (int u = 0; u < 2; ++u) {
            int lin  = u * 256 + t;        // 0..511
            int ch   = lin >> 7;           // 0..3
            int rem  = lin & 127;
            int row  = rem >> 5;           // 0..3  (input rows h0-1 .. h0+2)
            int col4 = rem & 31;
            int grow = h0 - 1 + row;
            float4 v = make_float4(0.f, 0.f, 0.f, 0.f);
            if (grow >= 0 && grow < HH)
                v = *(const float4*)(xb + (size_t)(cb + ch) * PLANE
                                     + grow * WW + (col4 << 2));
            *(float4*)&xs[buf][ch][row * WW + (col4 << 2)] = v;
        }
    };

    load_stage(0, 0);
    int buf = 0;
#pragma unroll
    for (int s = 0; s < CPG / STAGE; ++s) {
        __syncthreads();
        if (s + 1 < CPG / STAGE) load_stage(s + 1, buf ^ 1);

#pragma unroll
        for (int ch = 0; ch < STAGE; ++ch) {
            int c = c0 + s * STAGE + ch;
            const float* row0 = &xs[buf][ch][r * WW];   // row h-1 of patch

            float xp[9];
#pragma unroll
            for (int di = 0; di < 3; ++di)
#pragma unroll
                for (int dj = 0; dj < 3; ++dj) {
                    int ww2 = w - 1 + dj;
                    xp[di * 3 + dj] = (ww2 >= 0 && ww2 < WW)
                                      ? row0[di * WW + ww2] : 0.f;
                }

            unsigned long long acc0 = 0ull, acc1 = 0ull;
#pragma unroll
            for (int k = 0; k < 9; ++k) {
                unsigned vu = __float_as_uint(xp[k]);
                unsigned long long vv;
                asm("mov.b64 %0, {%1, %2};" : "=l"(vv) : "r"(vu), "r"(vu));
                asm("fma.rn.f32x2 %0, %1, %2, %0;"
                    : "+l"(acc0) : "l"(wk0[k]), "l"(vv));
                asm("fma.rn.f32x2 %0, %1, %2, %0;"
                    : "+l"(acc1) : "l"(wk1[k]), "l"(vv));
            }

            float2* op = (float2*)(out + (((size_t)(b * CC + c)) * H2 + 2 * h) * W2);
            op[w] = *(float2*)&acc0;
            op[(W2 / 2) + w] = *(float2*)&acc1;
        }
        buf ^= 1;
    }
}

extern "C" void kernel_launch(void* const* d_in, const int* in_sizes, int n_in,
                              void* d_out, int out_size) {
    const float* x    = (const float*)d_in[0];
    const float* Woff = (const float*)d_in[1];
    const float* boff = (const float*)d_in[2];
    float* out = (float*)d_out;

    mean1_kernel<<<dim3(PLANE / 4 / 256, 8, BB), 256>>>(x);
    mean2_kernel<<<(BB * PLANE / 4) / 256, 256>>>();
    kern_kernel<<<(BB * H2 * W2) / 256, 256>>>(Woff, boff);
    carafe_kernel<<<dim3(CC / CPG, HH / 2, BB), 256>>>(x, out);
}

// round 3
// speedup vs baseline: 2.1694x; 1.0457x over previous
#include <cuda_runtime.h>
#include <cstdint>

#define BB 2
#define CC 256
#define HH 128
#define WW 128
#define H2 256
#define W2 256
#define PLANE (HH * WW)

#define CPG 32        // channels per carafe block
#define STAGE 4       // channels per pipeline stage
#define NS (CPG / STAGE)
#define RSTR 132      // padded smem row stride (floats)
#define CHS (4 * RSTR + 4)   // per-channel smem floats (4 rows + right-halo pad)

// scratch (no allocations allowed)
__device__ float g_part[BB * 8 * PLANE];
__device__ float g_mean[BB * PLANE];
__device__ float g_kern[BB * 9 * H2 * W2];

// ---------------------------------------------------------------------------
// cp.async helpers
// ---------------------------------------------------------------------------
__device__ __forceinline__ void cp_async16(uint32_t dst_smem, const void* src, int src_sz) {
    asm volatile("cp.async.cg.shared.global [%0], [%1], 16, %2;\n"
                 :: "r"(dst_smem), "l"(src), "r"(src_sz));
}
__device__ __forceinline__ void cp_commit() {
    asm volatile("cp.async.commit_group;\n");
}
template <int N>
__device__ __forceinline__ void cp_wait() {
    asm volatile("cp.async.wait_group %0;\n" :: "n"(N));
}

// ---------------------------------------------------------------------------
// Kernel A1: partial channel sums (32 channels per block-slice, float4 pixels)
// ---------------------------------------------------------------------------
__global__ void mean1_kernel(const float* __restrict__ x) {
    int t  = threadIdx.x;
    int p4 = blockIdx.x * 256 + t;
    int cg = blockIdx.y;
    int b  = blockIdx.z;
    const float4* xp = (const float4*)x
                     + (size_t)(b * CC + cg * 32) * (PLANE / 4) + p4;
    float4 s = make_float4(0.f, 0.f, 0.f, 0.f);
#pragma unroll
    for (int c = 0; c < 32; ++c) {
        float4 v = xp[(size_t)c * (PLANE / 4)];
        s.x += v.x; s.y += v.y; s.z += v.z; s.w += v.w;
    }
    ((float4*)g_part)[((size_t)(b * 8 + cg)) * (PLANE / 4) + p4] = s;
}

// ---------------------------------------------------------------------------
// Kernel A2: combine partials -> mean
// ---------------------------------------------------------------------------
__global__ void mean2_kernel() {
    int idx = blockIdx.x * 256 + threadIdx.x;
    int b   = idx / (PLANE / 4);
    int p4  = idx % (PLANE / 4);
    float4 s = make_float4(0.f, 0.f, 0.f, 0.f);
#pragma unroll
    for (int g = 0; g < 8; ++g) {
        float4 v = ((const float4*)g_part)[((size_t)(b * 8 + g)) * (PLANE / 4) + p4];
        s.x += v.x; s.y += v.y; s.z += v.z; s.w += v.w;
    }
    const float sc = 1.0f / CC;
    s.x *= sc; s.y *= sc; s.z *= sc; s.w *= sc;
    ((float4*)g_mean)[(size_t)b * (PLANE / 4) + p4] = s;
}

// ---------------------------------------------------------------------------
// Kernel B: fused offset-conv + tanh + center + inverse-distance kernels +
//           grad gating + softmax  ->  g_kern[b,k,y,x]
// ---------------------------------------------------------------------------
__device__ __forceinline__ float fast_tanh(float x) {
    float e = __expf(2.0f * x);
    return __fdividef(e - 1.0f, e + 1.0f);
}

__global__ void kern_kernel(const float* __restrict__ Woff,
                            const float* __restrict__ boff) {
    __shared__ float sW[50];
    __shared__ float sb[2];
    int t = threadIdx.x;
    if (t < 50) sW[t] = Woff[t];
    if (t < 2) sb[t] = boff[t];
    __syncthreads();

    int idx = blockIdx.x * blockDim.x + t;
    int xq = idx & (W2 - 1);
    int y  = (idx >> 8) & (H2 - 1);
    int b  = idx >> 16;

    const float* m = g_mean + b * PLANE;

    float a0 = 0.f, a1 = 0.f;
#pragma unroll
    for (int u = 0; u < 5; ++u) {
        int Y = y - 2 + u;
        if (Y < 0 || Y >= H2) continue;
        int hh = Y >> 1;
#pragma unroll
        for (int v = 0; v < 5; ++v) {
            int X = xq - 2 + v;
            if (X < 0 || X >= W2) continue;
            float mv = m[hh * WW + (X >> 1)];
            a0 = fmaf(mv, sW[u * 5 + v], a0);
            a1 = fmaf(mv, sW[25 + u * 5 + v], a1);
        }
    }
    float s0 = ((xq & 1) ? 0.25f : -0.25f) + 0.25f * fast_tanh(a0 + sb[0]);
    float s1 = ((y  & 1) ? 0.25f : -0.25f) + 0.25f * fast_tanh(a1 + sb[1]);

    int hh = y >> 1, ww = xq >> 1;
    float mc = m[hh * WW + ww];

    float logit[9];
    float mx = -1e30f;
#pragma unroll
    for (int k = 0; k < 9; ++k) {
        int di = k / 3 - 1;
        int dj = k % 3 - 1;
        int hn = hh + di, wn = ww + dj;
        float pm = (hn >= 0 && hn < HH && wn >= 0 && wn < WW)
                   ? m[hn * WW + wn] : 0.f;
        float d = pm - mc;
        float e0 = s0 - (float)dj;
        float e1 = s1 - (float)di;
        float d2 = fmaf(e0, e0, fmaf(e1, e1, 0.2f));
        float kv = __fdividef(1.f, fmaf(d, d, 1.f) * d2);
        logit[k] = kv;
        mx = fmaxf(mx, kv);
    }
    float ev[9];
    float sum = 0.f;
#pragma unroll
    for (int k = 0; k < 9; ++k) { ev[k] = __expf(logit[k] - mx); sum += ev[k]; }
    float inv = __fdividef(1.f, sum);
#pragma unroll
    for (int k = 0; k < 9; ++k)
        g_kern[((b * 9 + k) * H2 + y) * W2 + xq] = ev[k] * inv;
}

// ---------------------------------------------------------------------------
// Kernel C: CARAFE apply.
// Block = (32-channel group, 2-input-row stripe, batch). 256 threads.
// Thread = one input pixel -> 2x2 output cell. 36 weights in regs (f32x2),
// x planes streamed via cp.async double buffer, padded smem rows (no
// boundary predicates), inline packed-FFMA accumulation.
// ---------------------------------------------------------------------------
__global__ void __launch_bounds__(256, 4)
carafe_kernel(const float* __restrict__ x, float* __restrict__ out) {
    __shared__ __align__(16) float xs[2][STAGE][CHS];

    int b  = blockIdx.z;
    int h0 = blockIdx.y * 2;
    int c0 = blockIdx.x * CPG;
    int t  = threadIdx.x;
    int r  = t >> 7;                  // 0..1 local input row
    int w  = t & 127;                 // input column
    int h  = h0 + r;

    // hoist the 36 softmax weights for this 2x2 output cell (packed f32x2)
    const unsigned long long* kp =
        (const unsigned long long*)(g_kern + (size_t)b * 9 * H2 * W2);
    unsigned long long wk0[9], wk1[9];
#pragma unroll
    for (int k = 0; k < 9; ++k) {
        wk0[k] = kp[((size_t)k * H2 + 2 * h)     * (W2 / 2) + w];
        wk1[k] = kp[((size_t)k * H2 + 2 * h + 1) * (W2 / 2) + w];
    }

    // zero halo cells once (both buffers): per row, left halo [3], right [132+...]
    if (t < 64) {
        int bufi = t >> 5, lt = t & 31;
        int ch = lt >> 3, rem = lt & 7, row = rem >> 1, side = rem & 1;
        xs[bufi][ch][row * RSTR + (side ? RSTR : 3)] = 0.f;
    }

    const float* xb = x + (size_t)b * CC * PLANE;

    // stage loader via cp.async: 4 ch x 4 rows x 32 float4 = 512 copies
    auto load_stage = [&](int s, int buf) {
        int cb = c0 + s * STAGE;
#pragma unroll
        for (int u = 0; u < 2; ++u) {
            int lin  = u * 256 + t;
            int ch   = lin >> 7;
            int rem  = lin & 127;
            int row  = rem >> 5;
            int col4 = rem & 31;
            int grow = h0 - 1 + row;
            int ok   = (grow >= 0 && grow < HH);
            const float* src = xb + (size_t)(cb + ch) * PLANE
                             + (ok ? grow : 0) * WW + (col4 << 2);
            uint32_t dst = (uint32_t)__cvta_generic_to_shared(
                &xs[buf][ch][row * RSTR + 4 + (col4 << 2)]);
            cp_async16(dst, src, ok ? 16 : 0);
        }
    };

    load_stage(0, 0);
    cp_commit();

#pragma unroll 1
    for (int s = 0; s < NS; ++s) {
        int buf = s & 1;
        __syncthreads();                          // prev compute done -> buf^1 reusable
        if (s + 1 < NS) { load_stage(s + 1, buf ^ 1); cp_commit(); cp_wait<1>(); }
        else           { cp_wait<0>(); }
        __syncthreads();                          // stage s smem visible to all

        int cbase = c0 + s * STAGE;
#pragma unroll
        for (int ch = 0; ch < STAGE; ++ch) {
            const float* base = &xs[buf][ch][r * RSTR + 4 + w];
            unsigned long long acc0 = 0ull, acc1 = 0ull;
#pragma unroll
            for (int di = 0; di < 3; ++di) {
                const float* rp = base + di * RSTR;
                float xv[3] = { rp[-1], rp[0], rp[1] };
#pragma unroll
                for (int dj = 0; dj < 3; ++dj) {
                    int k = di * 3 + dj;
                    unsigned vu = __float_as_uint(xv[dj]);
                    unsigned long long vv;
                    asm("mov.b64 %0, {%1, %2};" : "=l"(vv) : "r"(vu), "r"(vu));
                    asm("fma.rn.f32x2 %0, %1, %2, %0;"
                        : "+l"(acc0) : "l"(wk0[k]), "l"(vv));
                    asm("fma.rn.f32x2 %0, %1, %2, %0;"
                        : "+l"(acc1) : "l"(wk1[k]), "l"(vv));
                }
            }
            float2* op = (float2*)(out + (((size_t)(b * CC + cbase + ch)) * H2
                                          + 2 * h) * W2);
            op[w] = *(float2*)&acc0;
            op[(W2 / 2) + w] = *(float2*)&acc1;
        }
    }
}

extern "C" void kernel_launch(void* const* d_in, const int* in_sizes, int n_in,
                              void* d_out, int out_size) {
    const float* x    = (const float*)d_in[0];
    const float* Woff = (const float*)d_in[1];
    const float* boff = (const float*)d_in[2];
    float* out = (float*)d_out;

    mean1_kernel<<<dim3(PLANE / 4 / 256, 8, BB), 256>>>(x);
    mean2_kernel<<<(BB * PLANE / 4) / 256, 256>>>();
    kern_kernel<<<(BB * H2 * W2) / 256, 256>>>(Woff, boff);
    carafe_kernel<<<dim3(CC / CPG, HH / 2, BB), 256>>>(x, out);
}